// round 1
// baseline (speedup 1.0000x reference)
#include <cuda_runtime.h>
#include <cstdint>
#include <cstddef>

// Problem constants
#define Bc 4
#define Nc 128
#define Cc 512
#define Hc 8
#define Dc 64
#define SCALEc 6.25f          // D^-0.5 * 50 = 50/8
#define MTOT 65536            // B*N*N
#define NOUT 2560             // 5*C
#define KDIM 512
#define NELEM 33554432        // MTOT*KDIM
#define NROWS_SM 524288       // 32*128*128 softmax rows

// ---------------- scratch (static __device__, allocation-free) ----------------
__device__ float  g_qkv[(size_t)MTOT * NOUT];          // 640 MB: [m, 5C] m=b*16384+i*128+j
__device__ float  g_scores[(size_t)32 * 128 * 128 * 128]; // 256 MB: [bh, i, j, k]
__device__ double g_sum, g_sumsq;
__device__ float  g_mu, g_rsig;
__device__ float  g_wsum[NOUT];

// ---------------- stats ----------------
__global__ void k_zero() { g_sum = 0.0; g_sumsq = 0.0; }

__global__ void k_reduce(const float* __restrict__ x) {
    const float4* x4 = (const float4*)x;
    float s = 0.f, ss = 0.f;
    for (unsigned idx = blockIdx.x * blockDim.x + threadIdx.x; idx < NELEM / 4;
         idx += gridDim.x * blockDim.x) {
        float4 v = x4[idx];
        s  += v.x + v.y + v.z + v.w;
        ss += v.x * v.x + v.y * v.y + v.z * v.z + v.w * v.w;
    }
    double ds = (double)s, dss = (double)ss;
    for (int o = 16; o; o >>= 1) {
        ds  += __shfl_down_sync(0xffffffffu, ds, o);
        dss += __shfl_down_sync(0xffffffffu, dss, o);
    }
    __shared__ double sh0[8], sh1[8];
    int lane = threadIdx.x & 31, w = threadIdx.x >> 5;
    if (lane == 0) { sh0[w] = ds; sh1[w] = dss; }
    __syncthreads();
    if (threadIdx.x == 0) {
        double a = 0, b = 0;
        for (int i = 0; i < 8; i++) { a += sh0[i]; b += sh1[i]; }
        atomicAdd(&g_sum, a);
        atomicAdd(&g_sumsq, b);
    }
}

__global__ void k_finalize() {
    double cnt  = (double)NELEM;
    double mean = g_sum / cnt;
    double var  = (g_sumsq - g_sum * g_sum / cnt) / (cnt - 1.0);
    g_mu   = (float)mean;
    g_rsig = (float)(1.0 / sqrt(var));
}

__global__ void k_wsum(const float* __restrict__ w) {
    int n = blockIdx.x * blockDim.x + threadIdx.x;
    if (n >= NOUT) return;
    float s = 0.f;
    for (int k = 0; k < KDIM; k++) s += w[(size_t)k * NOUT + n];
    g_wsum[n] = s;
}

// ---------------- QKV GEMM: [65536,512] x [512,2560], normalized epilogue ----------------
__global__ __launch_bounds__(256) void k_gemm_qkv(const float* __restrict__ X,
                                                  const float* __restrict__ W) {
    __shared__ float As[8][128];   // [k][m]
    __shared__ float Bs[8][128];   // [k][n]
    const int bn = blockIdx.x * 128, bm = blockIdx.y * 128;
    const int tid = threadIdx.x, tx = tid & 15, ty = tid >> 4;
    const int ldA_m = tid >> 1, ldA_k = (tid & 1) * 4;
    const int ldB_k = tid >> 5, ldB_n = (tid & 31) * 4;
    float acc[8][8] = {};
    for (int k0 = 0; k0 < KDIM; k0 += 8) {
        float4 av = *(const float4*)&X[(size_t)(bm + ldA_m) * KDIM + k0 + ldA_k];
        float4 bv = *(const float4*)&W[(size_t)(k0 + ldB_k) * NOUT + bn + ldB_n];
        As[ldA_k + 0][ldA_m] = av.x; As[ldA_k + 1][ldA_m] = av.y;
        As[ldA_k + 2][ldA_m] = av.z; As[ldA_k + 3][ldA_m] = av.w;
        *(float4*)&Bs[ldB_k][ldB_n] = bv;
        __syncthreads();
#pragma unroll
        for (int kk = 0; kk < 8; kk++) {
            float a[8], b[8];
#pragma unroll
            for (int i = 0; i < 8; i++) a[i] = As[kk][ty * 8 + i];
#pragma unroll
            for (int j = 0; j < 8; j++) b[j] = Bs[kk][tx * 8 + j];
#pragma unroll
            for (int i = 0; i < 8; i++)
#pragma unroll
                for (int j = 0; j < 8; j++) acc[i][j] += a[i] * b[j];
        }
        __syncthreads();
    }
    const float mu = g_mu, rs = g_rsig;
#pragma unroll
    for (int i = 0; i < 8; i++) {
        int m = bm + ty * 8 + i;
#pragma unroll
        for (int j = 0; j < 8; j++) {
            int n = bn + tx * 8 + j;
            g_qkv[(size_t)m * NOUT + n] = (acc[i][j] - mu * g_wsum[n]) * rs;
        }
    }
}

// ---------------- scores term1: per (bh,i): S[j,k] = SCALE * q_i @ k1_i^T ----------------
// term2: per (bh,j): S[i,k] += SCALE * Q_j @ K2_j^T
// Both are 128x128x64; mode 0 = term1 (write), mode 1 = term2 (accumulate).
template <int MODE>
__global__ __launch_bounds__(256) void k_scores(float* __restrict__ scores) {
    const int blk = blockIdx.x;           // bh*128 + (i or j)
    const int bh = blk >> 7, fix = blk & 127;
    const int b = bh >> 3, h = bh & 7;
    __shared__ float qs[32][128];  // [d][row]
    __shared__ float ks[32][128];
    const int tid = threadIdx.x, tx = tid & 15, ty = tid >> 4;

    const float* qbase;
    const float* kbase;
    size_t rstride;
    if (MODE == 0) {  // fix = i ; rows j (q), k (k1); row stride 2560
        qbase = g_qkv + (size_t)(b * 16384 + fix * 128) * NOUT + h * 64;
        kbase = qbase + 512;
        rstride = NOUT;
    } else {          // fix = j ; rows i (q), k (k2); row stride 128*2560
        qbase = g_qkv + (size_t)(b * 16384 + fix) * NOUT + h * 64;
        kbase = qbase + 1024;
        rstride = (size_t)128 * NOUT;
    }
    float acc[8][8] = {};
    for (int d0 = 0; d0 < 64; d0 += 32) {
        for (int t = tid; t < 1024; t += 256) {
            int r = t >> 3, d4 = (t & 7) << 2;
            float4 qv = *(const float4*)(qbase + (size_t)r * rstride + d0 + d4);
            float4 kv = *(const float4*)(kbase + (size_t)r * rstride + d0 + d4);
            qs[d4 + 0][r] = qv.x; qs[d4 + 1][r] = qv.y; qs[d4 + 2][r] = qv.z; qs[d4 + 3][r] = qv.w;
            ks[d4 + 0][r] = kv.x; ks[d4 + 1][r] = kv.y; ks[d4 + 2][r] = kv.z; ks[d4 + 3][r] = kv.w;
        }
        __syncthreads();
#pragma unroll
        for (int dd = 0; dd < 32; dd++) {
            float a[8], c[8];
#pragma unroll
            for (int i = 0; i < 8; i++) a[i] = qs[dd][ty * 8 + i];
#pragma unroll
            for (int j = 0; j < 8; j++) c[j] = ks[dd][tx * 8 + j];
#pragma unroll
            for (int i = 0; i < 8; i++)
#pragma unroll
                for (int j = 0; j < 8; j++) acc[i][j] += a[i] * c[j];
        }
        __syncthreads();
    }
    if (MODE == 0) {
        float* out = scores + (size_t)blk * 16384;  // [j*128 + k]
#pragma unroll
        for (int i = 0; i < 8; i++) {
            float* row = out + (size_t)(ty * 8 + i) * 128 + tx * 8;
#pragma unroll
            for (int j = 0; j < 8; j++) row[j] = SCALEc * acc[i][j];
        }
    } else {
        // scores[bh, i, j=fix, k] : bh*2097152 + i*16384 + fix*128 + k
        float* out = scores + (size_t)bh * 2097152 + (size_t)fix * 128;
#pragma unroll
        for (int i = 0; i < 8; i++) {
            float* row = out + (size_t)(ty * 8 + i) * 16384 + tx * 8;
#pragma unroll
            for (int j = 0; j < 8; j++) row[j] += SCALEc * acc[i][j];
        }
    }
}

// ---------------- softmax over k (rows of 128), one warp per row ----------------
__global__ __launch_bounds__(256) void k_softmax(float* __restrict__ s) {
    unsigned warp = (blockIdx.x * blockDim.x + threadIdx.x) >> 5;
    int lane = threadIdx.x & 31;
    if (warp >= NROWS_SM) return;
    float* row = s + (size_t)warp * 128;
    float4 v = *(float4*)(row + lane * 4);
    float m = fmaxf(fmaxf(v.x, v.y), fmaxf(v.z, v.w));
    for (int o = 16; o; o >>= 1) m = fmaxf(m, __shfl_xor_sync(0xffffffffu, m, o));
    v.x = __expf(v.x - m); v.y = __expf(v.y - m);
    v.z = __expf(v.z - m); v.w = __expf(v.w - m);
    float sum = v.x + v.y + v.z + v.w;
    for (int o = 16; o; o >>= 1) sum += __shfl_xor_sync(0xffffffffu, sum, o);
    float inv = 1.f / sum;
    v.x *= inv; v.y *= inv; v.z *= inv; v.w *= inv;
    *(float4*)(row + lane * 4) = v;
}

// ---------------- output: MODE 0 per (bh,i): O[j,d] = attn_i @ v1_i  (write)
//                   MODE 1 per (bh,j): O[i,d] += attn[:,j,:] @ v2[:,j,:] (accumulate)
template <int MODE>
__global__ __launch_bounds__(256) void k_out(const float* __restrict__ scores,
                                             float* __restrict__ out) {
    const int blk = blockIdx.x;
    const int bh = blk >> 7, fix = blk & 127;
    const int b = bh >> 3, h = bh & 7;
    __shared__ float as_[32][128];  // [k][row]
    __shared__ float vs[32][64];    // [k][d]
    const int tid = threadIdx.x, tx = tid & 15, ty = tid >> 4;

    const float* arow;   // attention, element [row*astride + k]
    size_t astride;
    const float* vbase;  // v, row k: vbase + k*vstride + d
    size_t vstride;
    float* obase;        // output, element [row*ostride + d]
    size_t ostride;
    if (MODE == 0) {  // fix = i, row = j
        arow = scores + (size_t)blk * 16384;           astride = 128;
        vbase = g_qkv + (size_t)(b * 16384 + fix * 128) * NOUT + 1536 + h * 64;
        vstride = NOUT;
        obase = out + ((size_t)(b * 128 + fix) * 128) * Cc + h * 64;
        ostride = Cc;
    } else {          // fix = j, row = i
        arow = scores + (size_t)bh * 2097152 + (size_t)fix * 128;  astride = 16384;
        vbase = g_qkv + (size_t)(b * 16384 + fix) * NOUT + 2048 + h * 64;
        vstride = (size_t)128 * NOUT;
        obase = out + ((size_t)(b * 128) * 128 + fix) * Cc + h * 64;
        ostride = (size_t)128 * Cc;
    }

    float acc[8][4] = {};
    for (int k0 = 0; k0 < 128; k0 += 32) {
        for (int t = tid; t < 1024; t += 256) {
            int r = t >> 3, k4 = (t & 7) << 2;
            float4 av = *(const float4*)(arow + (size_t)r * astride + k0 + k4);
            as_[k4 + 0][r] = av.x; as_[k4 + 1][r] = av.y;
            as_[k4 + 2][r] = av.z; as_[k4 + 3][r] = av.w;
        }
        for (int t = tid; t < 512; t += 256) {
            int k = t >> 4, d4 = (t & 15) << 2;
            *(float4*)&vs[k][d4] = *(const float4*)(vbase + (size_t)(k0 + k) * vstride + d4);
        }
        __syncthreads();
#pragma unroll
        for (int kk = 0; kk < 32; kk++) {
            float a[8], c[4];
#pragma unroll
            for (int i = 0; i < 8; i++) a[i] = as_[kk][ty * 8 + i];
#pragma unroll
            for (int j = 0; j < 4; j++) c[j] = vs[kk][tx * 4 + j];
#pragma unroll
            for (int i = 0; i < 8; i++)
#pragma unroll
                for (int j = 0; j < 4; j++) acc[i][j] += a[i] * c[j];
        }
        __syncthreads();
    }
#pragma unroll
    for (int i = 0; i < 8; i++) {
        float* p = obase + (size_t)(ty * 8 + i) * ostride + tx * 4;
        if (MODE == 0) {
            float4 st = make_float4(acc[i][0], acc[i][1], acc[i][2], acc[i][3]);
            *(float4*)p = st;
        } else {
            float4 o = *(float4*)p;
            o.x += acc[i][0]; o.y += acc[i][1]; o.z += acc[i][2]; o.w += acc[i][3];
            *(float4*)p = o;
        }
    }
}

// ---------------- launch ----------------
extern "C" void kernel_launch(void* const* d_in, const int* in_sizes, int n_in,
                              void* d_out, int out_size) {
    const float* x = (const float*)d_in[0];
    const float* w = (const float*)d_in[1];
    float* out = (float*)d_out;

    float* scores;
    cudaGetSymbolAddress((void**)&scores, g_scores);

    k_zero<<<1, 1>>>();
    k_reduce<<<1024, 256>>>(x);
    k_finalize<<<1, 1>>>();
    k_wsum<<<(NOUT + 255) / 256, 256>>>(w);
    k_gemm_qkv<<<dim3(NOUT / 128, MTOT / 128), 256>>>(x, w);
    k_scores<0><<<4096, 256>>>(scores);
    k_scores<1><<<4096, 256>>>(scores);
    k_softmax<<<NROWS_SM / 8, 256>>>(scores);
    k_out<0><<<4096, 256>>>(scores, out);
    k_out<1><<<4096, 256>>>(scores, out);
}

// round 6
// speedup vs baseline: 1.7438x; 1.7438x over previous
#include <cuda_runtime.h>
#include <cuda_bf16.h>
#include <cstdint>
#include <cstddef>

#define Bc 4
#define Nc 128
#define Cc 512
#define Hc 8
#define Dc 64
#define SCALEc 6.25f
#define MTOT 65536
#define NOUT 2560
#define KDIM 512
#define NELEM 33554432
#define NROWS_SM 524288

// ---------------- scratch ----------------
__device__ float  g_qkv[(size_t)MTOT * NOUT];
__device__ float  g_scores[(size_t)32 * 128 * 128 * 128];
__device__ double g_sum, g_sumsq;
__device__ float  g_mu, g_rsig;
__device__ float  g_wsum[NOUT];

// ---------------- bf16 split helpers ----------------
__device__ __forceinline__ void split_bf(float v, __nv_bfloat16& h, __nv_bfloat16& l) {
    h = __float2bfloat16_rn(v);
    l = __float2bfloat16_rn(v - __bfloat162float(h));
}
__device__ __forceinline__ void mma_bf16(float c[4], const unsigned a[4], const unsigned b[2]) {
    asm volatile("mma.sync.aligned.m16n8k16.row.col.f32.bf16.bf16.f32 "
                 "{%0,%1,%2,%3},{%4,%5,%6,%7},{%8,%9},{%0,%1,%2,%3};"
                 : "+f"(c[0]), "+f"(c[1]), "+f"(c[2]), "+f"(c[3])
                 : "r"(a[0]), "r"(a[1]), "r"(a[2]), "r"(a[3]), "r"(b[0]), "r"(b[1]));
}

// ---------------- stats ----------------
__global__ void k_zero() { g_sum = 0.0; g_sumsq = 0.0; }

__global__ void k_reduce(const float* __restrict__ x) {
    const float4* x4 = (const float4*)x;
    float s = 0.f, ss = 0.f;
    for (unsigned idx = blockIdx.x * blockDim.x + threadIdx.x; idx < NELEM / 4;
         idx += gridDim.x * blockDim.x) {
        float4 v = x4[idx];
        s  += v.x + v.y + v.z + v.w;
        ss += v.x * v.x + v.y * v.y + v.z * v.z + v.w * v.w;
    }
    double ds = (double)s, dss = (double)ss;
    for (int o = 16; o; o >>= 1) {
        ds  += __shfl_down_sync(0xffffffffu, ds, o);
        dss += __shfl_down_sync(0xffffffffu, dss, o);
    }
    __shared__ double sh0[8], sh1[8];
    int lane = threadIdx.x & 31, w = threadIdx.x >> 5;
    if (lane == 0) { sh0[w] = ds; sh1[w] = dss; }
    __syncthreads();
    if (threadIdx.x == 0) {
        double a = 0, b = 0;
        for (int i = 0; i < 8; i++) { a += sh0[i]; b += sh1[i]; }
        atomicAdd(&g_sum, a);
        atomicAdd(&g_sumsq, b);
    }
}

__global__ void k_finalize() {
    double cnt  = (double)NELEM;
    double mean = g_sum / cnt;
    double var  = (g_sumsq - g_sum * g_sum / cnt) / (cnt - 1.0);
    g_mu   = (float)mean;
    g_rsig = (float)(1.0 / sqrt(var));
}

__global__ void k_wsum(const float* __restrict__ w) {
    int n = blockIdx.x * blockDim.x + threadIdx.x;
    if (n >= NOUT) return;
    float s = 0.f;
    for (int k = 0; k < KDIM; k++) s += w[(size_t)k * NOUT + n];
    g_wsum[n] = s;
}

// ---------------- QKV GEMM (bf16x3): [65536,512]x[512,2560] ----------------
#define LDK 18   // 16 k elements + 2 pad (bf16)
__global__ __launch_bounds__(256) void k_gemm_qkv_bf3(const float* __restrict__ X,
                                                      const float* __restrict__ W) {
    __shared__ __nv_bfloat16 Ah[128][LDK], Al[128][LDK];
    __shared__ __nv_bfloat16 Bh[128][LDK], Bl[128][LDK];   // [n][k]
    const int tid = threadIdx.x;
    const int warp = tid >> 5, lane = tid & 31;
    const int wr = warp >> 2, wc = warp & 3;   // 2x4 warps, warp tile 64x32
    const int bm = blockIdx.y * 128, bn = blockIdx.x * 128;
    float acc[4][4][4] = {};

    for (int k0 = 0; k0 < KDIM; k0 += 16) {
#pragma unroll
        for (int h = 0; h < 2; h++) {   // A: 128 rows x 16 k
            int idx = h * 256 + tid;
            int r = idx >> 2, q = (idx & 3) * 4;
            float4 v = *(const float4*)&X[(size_t)(bm + r) * KDIM + k0 + q];
            split_bf(v.x, Ah[r][q + 0], Al[r][q + 0]);
            split_bf(v.y, Ah[r][q + 1], Al[r][q + 1]);
            split_bf(v.z, Ah[r][q + 2], Al[r][q + 2]);
            split_bf(v.w, Ah[r][q + 3], Al[r][q + 3]);
        }
#pragma unroll
        for (int h = 0; h < 2; h++) {   // B: 16 k rows x 128 n, transpose to [n][k]
            int idx = h * 256 + tid;
            int kk = idx >> 5, nq = (idx & 31) * 4;
            float4 v = *(const float4*)&W[(size_t)(k0 + kk) * NOUT + bn + nq];
            split_bf(v.x, Bh[nq + 0][kk], Bl[nq + 0][kk]);
            split_bf(v.y, Bh[nq + 1][kk], Bl[nq + 1][kk]);
            split_bf(v.z, Bh[nq + 2][kk], Bl[nq + 2][kk]);
            split_bf(v.w, Bh[nq + 3][kk], Bl[nq + 3][kk]);
        }
        __syncthreads();
        const int c2 = 2 * (lane & 3), rsel = lane >> 2;
        unsigned ah[4][4], al[4][4], bh2[4][2], bl2[4][2];
#pragma unroll
        for (int i = 0; i < 4; i++) {
            int row = wr * 64 + i * 16 + rsel;
            ah[i][0] = *(const unsigned*)&Ah[row][c2];
            ah[i][1] = *(const unsigned*)&Ah[row + 8][c2];
            ah[i][2] = *(const unsigned*)&Ah[row][c2 + 8];
            ah[i][3] = *(const unsigned*)&Ah[row + 8][c2 + 8];
            al[i][0] = *(const unsigned*)&Al[row][c2];
            al[i][1] = *(const unsigned*)&Al[row + 8][c2];
            al[i][2] = *(const unsigned*)&Al[row][c2 + 8];
            al[i][3] = *(const unsigned*)&Al[row + 8][c2 + 8];
        }
#pragma unroll
        for (int j = 0; j < 4; j++) {
            int n = wc * 32 + j * 8 + rsel;
            bh2[j][0] = *(const unsigned*)&Bh[n][c2];
            bh2[j][1] = *(const unsigned*)&Bh[n][c2 + 8];
            bl2[j][0] = *(const unsigned*)&Bl[n][c2];
            bl2[j][1] = *(const unsigned*)&Bl[n][c2 + 8];
        }
#pragma unroll
        for (int i = 0; i < 4; i++)
#pragma unroll
            for (int j = 0; j < 4; j++) {
                mma_bf16(acc[i][j], ah[i], bh2[j]);
                mma_bf16(acc[i][j], ah[i], bl2[j]);
                mma_bf16(acc[i][j], al[i], bh2[j]);
            }
        __syncthreads();
    }
    const float mu = g_mu, rs = g_rsig;
#pragma unroll
    for (int i = 0; i < 4; i++) {
        int m0 = bm + wr * 64 + i * 16 + (lane >> 2);
#pragma unroll
        for (int j = 0; j < 4; j++) {
            int n0 = bn + wc * 32 + j * 8 + (lane & 3) * 2;
            float w0 = g_wsum[n0], w1 = g_wsum[n0 + 1];
            float2 v0 = make_float2((acc[i][j][0] - mu * w0) * rs,
                                    (acc[i][j][1] - mu * w1) * rs);
            float2 v1 = make_float2((acc[i][j][2] - mu * w0) * rs,
                                    (acc[i][j][3] - mu * w1) * rs);
            *(float2*)&g_qkv[(size_t)m0 * NOUT + n0] = v0;
            *(float2*)&g_qkv[(size_t)(m0 + 8) * NOUT + n0] = v1;
        }
    }
}

// ---------------- scores (bf16x3): 128x128x64 per block ----------------
template <int MODE>
__global__ __launch_bounds__(256) void k_scores_bf3(float* __restrict__ scores) {
    __shared__ __nv_bfloat16 Qh[128][LDK], Ql[128][LDK];
    __shared__ __nv_bfloat16 Kh[128][LDK], Kl[128][LDK];
    const int blk = blockIdx.x;
    const int bh = blk >> 7, fix = blk & 127;
    const int b = bh >> 3, h = bh & 7;
    const int tid = threadIdx.x;
    const int warp = tid >> 5, lane = tid & 31;
    const int wr = warp >> 2, wc = warp & 3;   // warp tile 64x32

    const float* qbase; const float* kbase; size_t rstride;
    if (MODE == 0) {
        qbase = g_qkv + (size_t)(b * 16384 + fix * 128) * NOUT + h * 64;
        kbase = qbase + 512;
        rstride = NOUT;
    } else {
        qbase = g_qkv + (size_t)(b * 16384 + fix) * NOUT + h * 64;
        kbase = qbase + 1024;
        rstride = (size_t)128 * NOUT;
    }
    float acc[4][4][4] = {};
    for (int d0 = 0; d0 < 64; d0 += 16) {
#pragma unroll
        for (int it = 0; it < 2; it++) {
            int idx = it * 256 + tid;
            int r = idx >> 2, q = (idx & 3) * 4;
            float4 qv = *(const float4*)(qbase + (size_t)r * rstride + d0 + q);
            float4 kv = *(const float4*)(kbase + (size_t)r * rstride + d0 + q);
            split_bf(qv.x, Qh[r][q + 0], Ql[r][q + 0]);
            split_bf(qv.y, Qh[r][q + 1], Ql[r][q + 1]);
            split_bf(qv.z, Qh[r][q + 2], Ql[r][q + 2]);
            split_bf(qv.w, Qh[r][q + 3], Ql[r][q + 3]);
            split_bf(kv.x, Kh[r][q + 0], Kl[r][q + 0]);
            split_bf(kv.y, Kh[r][q + 1], Kl[r][q + 1]);
            split_bf(kv.z, Kh[r][q + 2], Kl[r][q + 2]);
            split_bf(kv.w, Kh[r][q + 3], Kl[r][q + 3]);
        }
        __syncthreads();
        const int c2 = 2 * (lane & 3), rsel = lane >> 2;
        unsigned ah[4][4], al[4][4], bh2[4][2], bl2[4][2];
#pragma unroll
        for (int i = 0; i < 4; i++) {
            int row = wr * 64 + i * 16 + rsel;
            ah[i][0] = *(const unsigned*)&Qh[row][c2];
            ah[i][1] = *(const unsigned*)&Qh[row + 8][c2];
            ah[i][2] = *(const unsigned*)&Qh[row][c2 + 8];
            ah[i][3] = *(const unsigned*)&Qh[row + 8][c2 + 8];
            al[i][0] = *(const unsigned*)&Ql[row][c2];
            al[i][1] = *(const unsigned*)&Ql[row + 8][c2];
            al[i][2] = *(const unsigned*)&Ql[row][c2 + 8];
            al[i][3] = *(const unsigned*)&Ql[row + 8][c2 + 8];
        }
#pragma unroll
        for (int j = 0; j < 4; j++) {
            int n = wc * 32 + j * 8 + rsel;
            bh2[j][0] = *(const unsigned*)&Kh[n][c2];
            bh2[j][1] = *(const unsigned*)&Kh[n][c2 + 8];
            bl2[j][0] = *(const unsigned*)&Kl[n][c2];
            bl2[j][1] = *(const unsigned*)&Kl[n][c2 + 8];
        }
#pragma unroll
        for (int i = 0; i < 4; i++)
#pragma unroll
            for (int j = 0; j < 4; j++) {
                mma_bf16(acc[i][j], ah[i], bh2[j]);
                mma_bf16(acc[i][j], ah[i], bl2[j]);
                mma_bf16(acc[i][j], al[i], bh2[j]);
            }
        __syncthreads();
    }
#pragma unroll
    for (int i = 0; i < 4; i++) {
        int row = wr * 64 + i * 16 + (lane >> 2);
#pragma unroll
        for (int j = 0; j < 4; j++) {
            int col = wc * 32 + j * 8 + (lane & 3) * 2;
            if (MODE == 0) {
                float* p0 = scores + (size_t)blk * 16384 + (size_t)row * 128 + col;
                float* p1 = p0 + 8 * 128;
                *(float2*)p0 = make_float2(SCALEc * acc[i][j][0], SCALEc * acc[i][j][1]);
                *(float2*)p1 = make_float2(SCALEc * acc[i][j][2], SCALEc * acc[i][j][3]);
            } else {
                float* p0 = scores + (size_t)bh * 2097152 + (size_t)row * 16384 +
                            (size_t)fix * 128 + col;
                float* p1 = p0 + (size_t)8 * 16384;
                float2 o0 = *(float2*)p0, o1 = *(float2*)p1;
                o0.x += SCALEc * acc[i][j][0]; o0.y += SCALEc * acc[i][j][1];
                o1.x += SCALEc * acc[i][j][2]; o1.y += SCALEc * acc[i][j][3];
                *(float2*)p0 = o0; *(float2*)p1 = o1;
            }
        }
    }
}

// ---------------- softmax ----------------
__global__ __launch_bounds__(256) void k_softmax(float* __restrict__ s) {
    unsigned warp = (blockIdx.x * blockDim.x + threadIdx.x) >> 5;
    int lane = threadIdx.x & 31;
    if (warp >= NROWS_SM) return;
    float* row = s + (size_t)warp * 128;
    float4 v = *(float4*)(row + lane * 4);
    float m = fmaxf(fmaxf(v.x, v.y), fmaxf(v.z, v.w));
    for (int o = 16; o; o >>= 1) m = fmaxf(m, __shfl_xor_sync(0xffffffffu, m, o));
    v.x = __expf(v.x - m); v.y = __expf(v.y - m);
    v.z = __expf(v.z - m); v.w = __expf(v.w - m);
    float sum = v.x + v.y + v.z + v.w;
    for (int o = 16; o; o >>= 1) sum += __shfl_xor_sync(0xffffffffu, sum, o);
    float inv = 1.f / sum;
    v.x *= inv; v.y *= inv; v.z *= inv; v.w *= inv;
    *(float4*)(row + lane * 4) = v;
}

// ---------------- output (bf16x3): 128x64x128 per block ----------------
template <int MODE>
__global__ __launch_bounds__(256) void k_out_bf3(const float* __restrict__ scores,
                                                 float* __restrict__ out) {
    __shared__ __nv_bfloat16 Ath[128][LDK], Atl[128][LDK];   // attn [row][k]
    __shared__ __nv_bfloat16 Vh[64][LDK], Vl[64][LDK];       // v    [d][k]
    const int blk = blockIdx.x;
    const int bh = blk >> 7, fix = blk & 127;
    const int b = bh >> 3, h = bh & 7;
    const int tid = threadIdx.x;
    const int warp = tid >> 5, lane = tid & 31;
    const int wr = warp >> 2, wc = warp & 3;   // warp tile 64x16

    const float* arow; size_t astride;
    const float* vbase; size_t vstride;
    float* obase; size_t ostride;
    if (MODE == 0) {
        arow = scores + (size_t)blk * 16384;  astride = 128;
        vbase = g_qkv + (size_t)(b * 16384 + fix * 128) * NOUT + 1536 + h * 64;
        vstride = NOUT;
        obase = out + ((size_t)(b * 128 + fix) * 128) * Cc + h * 64;
        ostride = Cc;
    } else {
        arow = scores + (size_t)bh * 2097152 + (size_t)fix * 128;  astride = 16384;
        vbase = g_qkv + (size_t)(b * 16384 + fix) * NOUT + 2048 + h * 64;
        vstride = (size_t)128 * NOUT;
        obase = out + ((size_t)(b * 128) * 128 + fix) * Cc + h * 64;
        ostride = (size_t)128 * Cc;
    }

    float acc[4][2][4] = {};
    for (int k0 = 0; k0 < 128; k0 += 16) {
#pragma unroll
        for (int it = 0; it < 2; it++) {   // attn: 128 rows x 16 k
            int idx = it * 256 + tid;
            int r = idx >> 2, q = (idx & 3) * 4;
            float4 av = *(const float4*)(arow + (size_t)r * astride + k0 + q);
            split_bf(av.x, Ath[r][q + 0], Atl[r][q + 0]);
            split_bf(av.y, Ath[r][q + 1], Atl[r][q + 1]);
            split_bf(av.z, Ath[r][q + 2], Atl[r][q + 2]);
            split_bf(av.w, Ath[r][q + 3], Atl[r][q + 3]);
        }
        {   // v: 16 k rows x 64 d, transpose into [d][k]
            int kk = tid >> 4, d4 = (tid & 15) * 4;
            float4 vv = *(const float4*)(vbase + (size_t)(k0 + kk) * vstride + d4);
            split_bf(vv.x, Vh[d4 + 0][kk], Vl[d4 + 0][kk]);
            split_bf(vv.y, Vh[d4 + 1][kk], Vl[d4 + 1][kk]);
            split_bf(vv.z, Vh[d4 + 2][kk], Vl[d4 + 2][kk]);
            split_bf(vv.w, Vh[d4 + 3][kk], Vl[d4 + 3][kk]);
        }
        __syncthreads();
        const int c2 = 2 * (lane & 3), rsel = lane >> 2;
        unsigned ah[4][4], al[4][4], bh2[2][2], bl2[2][2];
#pragma unroll
        for (int i = 0; i < 4; i++) {
            int row = wr * 64 + i * 16 + rsel;
            ah[i][0] = *(const unsigned*)&Ath[row][c2];
            ah[i][1] = *(const unsigned*)&Ath[row + 8][c2];
            ah[i][2] = *(const unsigned*)&Ath[row][c2 + 8];
            ah[i][3] = *(const unsigned*)&Ath[row + 8][c2 + 8];
            al[i][0] = *(const unsigned*)&Atl[row][c2];
            al[i][1] = *(const unsigned*)&Atl[row + 8][c2];
            al[i][2] = *(const unsigned*)&Atl[row][c2 + 8];
            al[i][3] = *(const unsigned*)&Atl[row + 8][c2 + 8];
        }
#pragma unroll
        for (int j = 0; j < 2; j++) {
            int n = wc * 16 + j * 8 + rsel;
            bh2[j][0] = *(const unsigned*)&Vh[n][c2];
            bh2[j][1] = *(const unsigned*)&Vh[n][c2 + 8];
            bl2[j][0] = *(const unsigned*)&Vl[n][c2];
            bl2[j][1] = *(const unsigned*)&Vl[n][c2 + 8];
        }
#pragma unroll
        for (int i = 0; i < 4; i++)
#pragma unroll
            for (int j = 0; j < 2; j++) {
                mma_bf16(acc[i][j], ah[i], bh2[j]);
                mma_bf16(acc[i][j], ah[i], bl2[j]);
                mma_bf16(acc[i][j], al[i], bh2[j]);
            }
        __syncthreads();
    }
#pragma unroll
    for (int i = 0; i < 4; i++) {
        int row = wr * 64 + i * 16 + (lane >> 2);
#pragma unroll
        for (int j = 0; j < 2; j++) {
            int col = wc * 16 + j * 8 + (lane & 3) * 2;
            float* p0 = obase + (size_t)row * ostride + col;
            float* p1 = obase + (size_t)(row + 8) * ostride + col;
            if (MODE == 0) {
                *(float2*)p0 = make_float2(acc[i][j][0], acc[i][j][1]);
                *(float2*)p1 = make_float2(acc[i][j][2], acc[i][j][3]);
            } else {
                float2 o0 = *(float2*)p0, o1 = *(float2*)p1;
                o0.x += acc[i][j][0]; o0.y += acc[i][j][1];
                o1.x += acc[i][j][2]; o1.y += acc[i][j][3];
                *(float2*)p0 = o0; *(float2*)p1 = o1;
            }
        }
    }
}

// ---------------- launch ----------------
extern "C" void kernel_launch(void* const* d_in, const int* in_sizes, int n_in,
                              void* d_out, int out_size) {
    const float* x = (const float*)d_in[0];
    const float* w = (const float*)d_in[1];
    float* out = (float*)d_out;

    float* scores;
    cudaGetSymbolAddress((void**)&scores, g_scores);

    k_zero<<<1, 1>>>();
    k_reduce<<<1024, 256>>>(x);
    k_finalize<<<1, 1>>>();
    k_wsum<<<(NOUT + 255) / 256, 256>>>(w);
    k_gemm_qkv_bf3<<<dim3(NOUT / 128, MTOT / 128), 256>>>(x, w);
    k_scores_bf3<0><<<4096, 256>>>(scores);
    k_scores_bf3<1><<<4096, 256>>>(scores);
    k_softmax<<<NROWS_SM / 8, 256>>>(scores);
    k_out_bf3<0><<<4096, 256>>>(scores, out);
    k_out_bf3<1><<<4096, 256>>>(scores, out);
}

// round 12
// speedup vs baseline: 2.1973x; 1.2601x over previous
#include <cuda_runtime.h>
#include <cuda_bf16.h>
#include <cstdint>
#include <cstddef>

#define Bc 4
#define Nc 128
#define Cc 512
#define Hc 8
#define Dc 64
#define SCALEc 6.25f
#define MTOT 65536
#define NOUT 2560
#define KDIM 512
#define NELEM 33554432

typedef unsigned short ushort_t;

// ---------------- scratch ----------------
__device__ float    g_qkv[(size_t)MTOT * NOUT];            // fp32 qkv
__device__ float    g_scores[(size_t)32 * 128 * 128 * 128]; // term1 -> attn (in place)
__device__ ushort_t g_xh[(size_t)MTOT * KDIM];             // normalized x, bf16 hi
__device__ ushort_t g_xl[(size_t)MTOT * KDIM];             // bf16 lo
__device__ ushort_t g_wth[(size_t)NOUT * KDIM];            // W^T hi  [n][k]
__device__ ushort_t g_wtl[(size_t)NOUT * KDIM];            // W^T lo
__device__ double g_sum, g_sumsq;
__device__ float  g_mu, g_rsig;

// ---------------- helpers ----------------
__device__ __forceinline__ void split_us(float v, ushort_t& h, ushort_t& l) {
    __nv_bfloat16 hb = __float2bfloat16_rn(v);
    float r = v - __bfloat162float(hb);
    __nv_bfloat16 lb = __float2bfloat16_rn(r);
    h = __bfloat16_as_ushort(hb);
    l = __bfloat16_as_ushort(lb);
}
__device__ __forceinline__ void split_bf(float v, __nv_bfloat16& h, __nv_bfloat16& l) {
    h = __float2bfloat16_rn(v);
    l = __float2bfloat16_rn(v - __bfloat162float(h));
}
__device__ __forceinline__ void mma_bf16(float c[4], const unsigned a[4], const unsigned b[2]) {
    asm volatile("mma.sync.aligned.m16n8k16.row.col.f32.bf16.bf16.f32 "
                 "{%0,%1,%2,%3},{%4,%5,%6,%7},{%8,%9},{%0,%1,%2,%3};"
                 : "+f"(c[0]), "+f"(c[1]), "+f"(c[2]), "+f"(c[3])
                 : "r"(a[0]), "r"(a[1]), "r"(a[2]), "r"(a[3]), "r"(b[0]), "r"(b[1]));
}
__device__ __forceinline__ void mma_tf32(float c[4], const unsigned a[4], const unsigned b[2]) {
    asm volatile("mma.sync.aligned.m16n8k8.row.col.f32.tf32.tf32.f32 "
                 "{%0,%1,%2,%3},{%4,%5,%6,%7},{%8,%9},{%0,%1,%2,%3};"
                 : "+f"(c[0]), "+f"(c[1]), "+f"(c[2]), "+f"(c[3])
                 : "r"(a[0]), "r"(a[1]), "r"(a[2]), "r"(a[3]), "r"(b[0]), "r"(b[1]));
}
__device__ __forceinline__ unsigned f2tf(float f) {
    unsigned r; asm("cvt.rna.tf32.f32 %0, %1;" : "=r"(r) : "f"(f)); return r;
}
__device__ __forceinline__ void split_tf(float v, unsigned& h, unsigned& l) {
    asm("cvt.rna.tf32.f32 %0, %1;" : "=r"(h) : "f"(v));
    float hf = __uint_as_float(h);
    asm("cvt.rna.tf32.f32 %0, %1;" : "=r"(l) : "f"(v - hf));
}
__device__ __forceinline__ void cpa16(unsigned saddr, const void* g) {
    asm volatile("cp.async.cg.shared.global [%0], [%1], 16;\n" :: "r"(saddr), "l"(g));
}

// ---------------- stats ----------------
__global__ void k_zero() { g_sum = 0.0; g_sumsq = 0.0; }

__global__ void k_reduce(const float* __restrict__ x) {
    const float4* x4 = (const float4*)x;
    float s = 0.f, ss = 0.f;
    for (unsigned idx = blockIdx.x * blockDim.x + threadIdx.x; idx < NELEM / 4;
         idx += gridDim.x * blockDim.x) {
        float4 v = x4[idx];
        s  += v.x + v.y + v.z + v.w;
        ss += v.x * v.x + v.y * v.y + v.z * v.z + v.w * v.w;
    }
    double ds = (double)s, dss = (double)ss;
    for (int o = 16; o; o >>= 1) {
        ds  += __shfl_down_sync(0xffffffffu, ds, o);
        dss += __shfl_down_sync(0xffffffffu, dss, o);
    }
    __shared__ double sh0[8], sh1[8];
    int lane = threadIdx.x & 31, w = threadIdx.x >> 5;
    if (lane == 0) { sh0[w] = ds; sh1[w] = dss; }
    __syncthreads();
    if (threadIdx.x == 0) {
        double a = 0, b = 0;
        for (int i = 0; i < 8; i++) { a += sh0[i]; b += sh1[i]; }
        atomicAdd(&g_sum, a);
        atomicAdd(&g_sumsq, b);
    }
}

__global__ void k_finalize() {
    double cnt  = (double)NELEM;
    double mean = g_sum / cnt;
    double var  = (g_sumsq - g_sum * g_sum / cnt) / (cnt - 1.0);
    g_mu   = (float)mean;
    g_rsig = (float)(1.0 / sqrt(var));
}

// ---------------- prep: normalize + split X ----------------
__global__ __launch_bounds__(256) void k_prep_x(const float* __restrict__ x) {
    const float mu = g_mu, rs = g_rsig;
    const float4* x4 = (const float4*)x;
    for (unsigned idx = blockIdx.x * blockDim.x + threadIdx.x; idx < NELEM / 4;
         idx += gridDim.x * blockDim.x) {
        float4 v = x4[idx];
        ushort4 h, l;
        split_us((v.x - mu) * rs, h.x, l.x);
        split_us((v.y - mu) * rs, h.y, l.y);
        split_us((v.z - mu) * rs, h.z, l.z);
        split_us((v.w - mu) * rs, h.w, l.w);
        ((ushort4*)g_xh)[idx] = h;
        ((ushort4*)g_xl)[idx] = l;
    }
}

// ---------------- prep: split + transpose W -> [n][k] ----------------
__global__ __launch_bounds__(256) void k_prep_w(const float* __restrict__ w) {
    unsigned idx = blockIdx.x * blockDim.x + threadIdx.x;
    if (idx >= (unsigned)NOUT * KDIM) return;
    unsigned n = idx >> 9, k = idx & 511;
    float v = w[(size_t)k * NOUT + n];
    split_us(v, g_wth[idx], g_wtl[idx]);
}

// ---------------- QKV GEMM: pure bf16, double-buffered cp.async ----------------
// smem: 2 stages x 2 parts x 128 rows x GLDA(=16) shorts x 2 operands = 32768 B
// GLDA=16 -> 32 B row stride, every cp.async dst 16B-aligned.
#define GK 16
#define GLDA 16
__global__ __launch_bounds__(256) void k_gemm2() {
    __shared__ ushort_t sA[2][2][128 * GLDA];
    __shared__ ushort_t sB[2][2][128 * GLDA];
    const int tid = threadIdx.x;
    const int warp = tid >> 5, lane = tid & 31;
    const int wr = warp >> 2, wc = warp & 3;   // warp tile 64x32
    const int bm = blockIdx.y * 128, bn = blockIdx.x * 128;
    const unsigned sAb = (unsigned)__cvta_generic_to_shared(&sA[0][0][0]);
    const unsigned sBb = (unsigned)__cvta_generic_to_shared(&sB[0][0][0]);
    float acc[4][4][4] = {};

    const ushort_t* gA[2] = { g_xh, g_xl };
    const ushort_t* gB[2] = { g_wth, g_wtl };

    // one stage part = 128 rows x 16 shorts = 4096 B; 256 threads x 16 B
    auto loadstage = [&](int st, int k0) {
        int row = tid >> 1, off = (tid & 1) * 8;
#pragma unroll
        for (int p = 0; p < 2; p++) {
            unsigned so = (unsigned)(((st * 2 + p) * 128 * GLDA) + row * GLDA + off) * 2;
            cpa16(sAb + so, gA[p] + (size_t)(bm + row) * KDIM + k0 + off);
            cpa16(sBb + so, gB[p] + (size_t)(bn + row) * KDIM + k0 + off);
        }
    };

    loadstage(0, 0);
    asm volatile("cp.async.commit_group;");

    int buf = 0;
    for (int it = 0; it < KDIM / GK; it++) {
        if (it + 1 < KDIM / GK) {
            loadstage(buf ^ 1, (it + 1) * GK);
            asm volatile("cp.async.commit_group;");
            asm volatile("cp.async.wait_group 1;");
        } else {
            asm volatile("cp.async.wait_group 0;");
        }
        __syncthreads();

        const ushort_t* Ah = &sA[buf][0][0];
        const ushort_t* Al = &sA[buf][1][0];
        const ushort_t* Bh = &sB[buf][0][0];
        const ushort_t* Bl = &sB[buf][1][0];
        const int rsel = lane >> 2;
        const int c2 = 2 * (lane & 3);
        unsigned ah[4][4], al[4][4], bh2[4][2], bl2[4][2];
#pragma unroll
        for (int i = 0; i < 4; i++) {
            int row = wr * 64 + i * 16 + rsel;
            ah[i][0] = *(const unsigned*)&Ah[row * GLDA + c2];
            ah[i][1] = *(const unsigned*)&Ah[(row + 8) * GLDA + c2];
            ah[i][2] = *(const unsigned*)&Ah[row * GLDA + c2 + 8];
            ah[i][3] = *(const unsigned*)&Ah[(row + 8) * GLDA + c2 + 8];
            al[i][0] = *(const unsigned*)&Al[row * GLDA + c2];
            al[i][1] = *(const unsigned*)&Al[(row + 8) * GLDA + c2];
            al[i][2] = *(const unsigned*)&Al[row * GLDA + c2 + 8];
            al[i][3] = *(const unsigned*)&Al[(row + 8) * GLDA + c2 + 8];
        }
#pragma unroll
        for (int j = 0; j < 4; j++) {
            int n = wc * 32 + j * 8 + rsel;
            bh2[j][0] = *(const unsigned*)&Bh[n * GLDA + c2];
            bh2[j][1] = *(const unsigned*)&Bh[n * GLDA + c2 + 8];
            bl2[j][0] = *(const unsigned*)&Bl[n * GLDA + c2];
            bl2[j][1] = *(const unsigned*)&Bl[n * GLDA + c2 + 8];
        }
#pragma unroll
        for (int i = 0; i < 4; i++)
#pragma unroll
            for (int j = 0; j < 4; j++) {
                mma_bf16(acc[i][j], ah[i], bh2[j]);
                mma_bf16(acc[i][j], ah[i], bl2[j]);
                mma_bf16(acc[i][j], al[i], bh2[j]);
            }
        __syncthreads();
        buf ^= 1;
    }
#pragma unroll
    for (int i = 0; i < 4; i++) {
        int m0 = bm + wr * 64 + i * 16 + (lane >> 2);
#pragma unroll
        for (int j = 0; j < 4; j++) {
            int n0 = bn + wc * 32 + j * 8 + (lane & 3) * 2;
            *(float2*)&g_qkv[(size_t)m0 * NOUT + n0] = make_float2(acc[i][j][0], acc[i][j][1]);
            *(float2*)&g_qkv[(size_t)(m0 + 8) * NOUT + n0] = make_float2(acc[i][j][2], acc[i][j][3]);
        }
    }
}

// ---------------- scores term1 (bf16x3, write scratch) ----------------
#define LDK 18
__global__ __launch_bounds__(256) void k_scores1(float* __restrict__ scores) {
    __shared__ __nv_bfloat16 Qh[128][LDK], Ql[128][LDK];
    __shared__ __nv_bfloat16 Kh[128][LDK], Kl[128][LDK];
    const int blk = blockIdx.x;
    const int bh = blk >> 7, fix = blk & 127;
    const int b = bh >> 3, h = bh & 7;
    const int tid = threadIdx.x;
    const int warp = tid >> 5, lane = tid & 31;
    const int wr = warp >> 2, wc = warp & 3;

    const float* qbase = g_qkv + (size_t)(b * 16384 + fix * 128) * NOUT + h * 64;
    const float* kbase = qbase + 512;
    const size_t rstride = NOUT;

    float acc[4][4][4] = {};
    for (int d0 = 0; d0 < 64; d0 += 16) {
#pragma unroll
        for (int it = 0; it < 2; it++) {
            int idx = it * 256 + tid;
            int r = idx >> 2, q = (idx & 3) * 4;
            float4 qv = *(const float4*)(qbase + (size_t)r * rstride + d0 + q);
            float4 kv = *(const float4*)(kbase + (size_t)r * rstride + d0 + q);
            split_bf(qv.x, Qh[r][q + 0], Ql[r][q + 0]);
            split_bf(qv.y, Qh[r][q + 1], Ql[r][q + 1]);
            split_bf(qv.z, Qh[r][q + 2], Ql[r][q + 2]);
            split_bf(qv.w, Qh[r][q + 3], Ql[r][q + 3]);
            split_bf(kv.x, Kh[r][q + 0], Kl[r][q + 0]);
            split_bf(kv.y, Kh[r][q + 1], Kl[r][q + 1]);
            split_bf(kv.z, Kh[r][q + 2], Kl[r][q + 2]);
            split_bf(kv.w, Kh[r][q + 3], Kl[r][q + 3]);
        }
        __syncthreads();
        const int c2 = 2 * (lane & 3), rsel = lane >> 2;
        unsigned ah[4][4], al[4][4], bh2[4][2], bl2[4][2];
#pragma unroll
        for (int i = 0; i < 4; i++) {
            int row = wr * 64 + i * 16 + rsel;
            ah[i][0] = *(const unsigned*)&Qh[row][c2];
            ah[i][1] = *(const unsigned*)&Qh[row + 8][c2];
            ah[i][2] = *(const unsigned*)&Qh[row][c2 + 8];
            ah[i][3] = *(const unsigned*)&Qh[row + 8][c2 + 8];
            al[i][0] = *(const unsigned*)&Ql[row][c2];
            al[i][1] = *(const unsigned*)&Ql[row + 8][c2];
            al[i][2] = *(const unsigned*)&Ql[row][c2 + 8];
            al[i][3] = *(const unsigned*)&Ql[row + 8][c2 + 8];
        }
#pragma unroll
        for (int j = 0; j < 4; j++) {
            int n = wc * 32 + j * 8 + rsel;
            bh2[j][0] = *(const unsigned*)&Kh[n][c2];
            bh2[j][1] = *(const unsigned*)&Kh[n][c2 + 8];
            bl2[j][0] = *(const unsigned*)&Kl[n][c2];
            bl2[j][1] = *(const unsigned*)&Kl[n][c2 + 8];
        }
#pragma unroll
        for (int i = 0; i < 4; i++)
#pragma unroll
            for (int j = 0; j < 4; j++) {
                mma_bf16(acc[i][j], ah[i], bh2[j]);
                mma_bf16(acc[i][j], ah[i], bl2[j]);
                mma_bf16(acc[i][j], al[i], bh2[j]);
            }
        __syncthreads();
    }
#pragma unroll
    for (int i = 0; i < 4; i++) {
        int row = wr * 64 + i * 16 + (lane >> 2);
#pragma unroll
        for (int j = 0; j < 4; j++) {
            int col = wc * 32 + j * 8 + (lane & 3) * 2;
            float* p0 = scores + (size_t)blk * 16384 + (size_t)row * 128 + col;
            float* p1 = p0 + 8 * 128;
            *(float2*)p0 = make_float2(SCALEc * acc[i][j][0], SCALEc * acc[i][j][1]);
            *(float2*)p1 = make_float2(SCALEc * acc[i][j][2], SCALEc * acc[i][j][3]);
        }
    }
}

// ---------------- scores term2 + softmax (fused), in-place attn ----------------
__global__ __launch_bounds__(256) void k_scores2_sm(float* __restrict__ scores) {
    __shared__ __nv_bfloat16 Qh[128][LDK], Ql[128][LDK];
    __shared__ __nv_bfloat16 Kh[128][LDK], Kl[128][LDK];
    __shared__ float rmax[128][4];
    __shared__ float rsum[128][4];
    const int blk = blockIdx.x;
    const int bh = blk >> 7, fix = blk & 127;       // fix = j
    const int b = bh >> 3, h = bh & 7;
    const int tid = threadIdx.x;
    const int warp = tid >> 5, lane = tid & 31;
    const int wr = warp >> 2, wc = warp & 3;

    const float* qbase = g_qkv + (size_t)(b * 16384 + fix) * NOUT + h * 64;
    const float* kbase = qbase + 1024;
    const size_t rstride = (size_t)128 * NOUT;

    float acc[4][4][4] = {};
    for (int d0 = 0; d0 < 64; d0 += 16) {
#pragma unroll
        for (int it = 0; it < 2; it++) {
            int idx = it * 256 + tid;
            int r = idx >> 2, q = (idx & 3) * 4;
            float4 qv = *(const float4*)(qbase + (size_t)r * rstride + d0 + q);
            float4 kv = *(const float4*)(kbase + (size_t)r * rstride + d0 + q);
            split_bf(qv.x, Qh[r][q + 0], Ql[r][q + 0]);
            split_bf(qv.y, Qh[r][q + 1], Ql[r][q + 1]);
            split_bf(qv.z, Qh[r][q + 2], Ql[r][q + 2]);
            split_bf(qv.w, Qh[r][q + 3], Ql[r][q + 3]);
            split_bf(kv.x, Kh[r][q + 0], Kl[r][q + 0]);
            split_bf(kv.y, Kh[r][q + 1], Kl[r][q + 1]);
            split_bf(kv.z, Kh[r][q + 2], Kl[r][q + 2]);
            split_bf(kv.w, Kh[r][q + 3], Kl[r][q + 3]);
        }
        __syncthreads();
        const int c2 = 2 * (lane & 3), rsel = lane >> 2;
        unsigned ah[4][4], al[4][4], bh2[4][2], bl2[4][2];
#pragma unroll
        for (int i = 0; i < 4; i++) {
            int row = wr * 64 + i * 16 + rsel;
            ah[i][0] = *(const unsigned*)&Qh[row][c2];
            ah[i][1] = *(const unsigned*)&Qh[row + 8][c2];
            ah[i][2] = *(const unsigned*)&Qh[row][c2 + 8];
            ah[i][3] = *(const unsigned*)&Qh[row + 8][c2 + 8];
            al[i][0] = *(const unsigned*)&Ql[row][c2];
            al[i][1] = *(const unsigned*)&Ql[row + 8][c2];
            al[i][2] = *(const unsigned*)&Ql[row][c2 + 8];
            al[i][3] = *(const unsigned*)&Ql[row + 8][c2 + 8];
        }
#pragma unroll
        for (int j = 0; j < 4; j++) {
            int n = wc * 32 + j * 8 + rsel;
            bh2[j][0] = *(const unsigned*)&Kh[n][c2];
            bh2[j][1] = *(const unsigned*)&Kh[n][c2 + 8];
            bl2[j][0] = *(const unsigned*)&Kl[n][c2];
            bl2[j][1] = *(const unsigned*)&Kl[n][c2 + 8];
        }
#pragma unroll
        for (int i = 0; i < 4; i++)
#pragma unroll
            for (int j = 0; j < 4; j++) {
                mma_bf16(acc[i][j], ah[i], bh2[j]);
                mma_bf16(acc[i][j], ah[i], bl2[j]);
                mma_bf16(acc[i][j], al[i], bh2[j]);
            }
        __syncthreads();
    }

    // epilogue: s = SCALE*acc + term1, softmax over k (full row across 4 warps), write attn
    const int rsel = lane >> 2;
    float* base = scores + (size_t)bh * 2097152 + (size_t)fix * 128;
#pragma unroll
    for (int t = 0; t < 4; t++) {
        int row = wr * 64 + t * 16 + rsel;
#pragma unroll
        for (int j = 0; j < 4; j++) {
            int col = wc * 32 + j * 8 + (lane & 3) * 2;
            float2 o0 = *(float2*)(base + (size_t)row * 16384 + col);
            float2 o1 = *(float2*)(base + (size_t)(row + 8) * 16384 + col);
            acc[t][j][0] = SCALEc * acc[t][j][0] + o0.x;
            acc[t][j][1] = SCALEc * acc[t][j][1] + o0.y;
            acc[t][j][2] = SCALEc * acc[t][j][2] + o1.x;
            acc[t][j][3] = SCALEc * acc[t][j][3] + o1.y;
        }
    }
#pragma unroll
    for (int t = 0; t < 4; t++) {
#pragma unroll
        for (int r = 0; r < 2; r++) {
            float m = -1e30f;
#pragma unroll
            for (int j = 0; j < 4; j++)
                m = fmaxf(m, fmaxf(acc[t][j][2 * r], acc[t][j][2 * r + 1]));
            m = fmaxf(m, __shfl_xor_sync(0xffffffffu, m, 1));
            m = fmaxf(m, __shfl_xor_sync(0xffffffffu, m, 2));
            if ((lane & 3) == 0) rmax[wr * 64 + t * 16 + rsel + r * 8][wc] = m;
        }
    }
    __syncthreads();
#pragma unroll
    for (int t = 0; t < 4; t++) {
#pragma unroll
        for (int r = 0; r < 2; r++) {
            int row = wr * 64 + t * 16 + rsel + r * 8;
            float4 mv = *(float4*)rmax[row];
            float gm = fmaxf(fmaxf(mv.x, mv.y), fmaxf(mv.z, mv.w));
            float ls = 0.f;
#pragma unroll
            for (int j = 0; j < 4; j++) {
                float e0 = __expf(acc[t][j][2 * r] - gm);
                float e1 = __expf(acc[t][j][2 * r + 1] - gm);
                acc[t][j][2 * r] = e0; acc[t][j][2 * r + 1] = e1;
                ls += e0 + e1;
            }
            ls += __shfl_xor_sync(0xffffffffu, ls, 1);
            ls += __shfl_xor_sync(0xffffffffu, ls, 2);
            if ((lane & 3) == 0) rsum[row][wc] = ls;
        }
    }
    __syncthreads();
#pragma unroll
    for (int t = 0; t < 4; t++) {
        int row = wr * 64 + t * 16 + rsel;
        float4 s0 = *(float4*)rsum[row];
        float4 s1 = *(float4*)rsum[row + 8];
        float inv0 = 1.f / (s0.x + s0.y + s0.z + s0.w);
        float inv1 = 1.f / (s1.x + s1.y + s1.z + s1.w);
#pragma unroll
        for (int j = 0; j < 4; j++) {
            int col = wc * 32 + j * 8 + (lane & 3) * 2;
            *(float2*)(base + (size_t)row * 16384 + col) =
                make_float2(acc[t][j][0] * inv0, acc[t][j][1] * inv0);
            *(float2*)(base + (size_t)(row + 8) * 16384 + col) =
                make_float2(acc[t][j][2] * inv1, acc[t][j][3] * inv1);
        }
    }
}

// ---------------- output (tf32, attn single + v split) ----------------
#define OPAD 36
#define VPAD 68
template <int MODE>
__global__ __launch_bounds__(256) void k_out_tf(const float* __restrict__ scores,
                                                float* __restrict__ out) {
    __shared__ unsigned As_[128 * OPAD];      // attn tf32 [row][k<=32]
    __shared__ unsigned Vh[32 * VPAD];        // v hi [k][d<=64]
    __shared__ unsigned Vl[32 * VPAD];
    const int blk = blockIdx.x;
    const int bh = blk >> 7, fix = blk & 127;
    const int b = bh >> 3, h = bh & 7;
    const int tid = threadIdx.x;
    const int warp = tid >> 5, lane = tid & 31;
    const int wr = warp >> 2, wc = warp & 3;   // warp tile 64x16

    const float* arow; size_t astride;
    const float* vbase; size_t vstride;
    float* obase; size_t ostride;
    if (MODE == 0) {
        arow = scores + (size_t)blk * 16384;  astride = 128;
        vbase = g_qkv + (size_t)(b * 16384 + fix * 128) * NOUT + 1536 + h * 64;
        vstride = NOUT;
        obase = out + ((size_t)(b * 128 + fix) * 128) * Cc + h * 64;
        ostride = Cc;
    } else {
        arow = scores + (size_t)bh * 2097152 + (size_t)fix * 128;  astride = 16384;
        vbase = g_qkv + (size_t)(b * 16384 + fix) * NOUT + 2048 + h * 64;
        vstride = (size_t)128 * NOUT;
        obase = out + ((size_t)(b * 128) * 128 + fix) * Cc + h * 64;
        ostride = (size_t)128 * Cc;
    }

    float acc[4][2][4] = {};
    for (int k0 = 0; k0 < 128; k0 += 32) {
#pragma unroll
        for (int it = 0; it < 4; it++) {
            int idx = it * 256 + tid;
            int r = idx >> 3, k4 = (idx & 7) * 4;
            float4 av = *(const float4*)(arow + (size_t)r * astride + k0 + k4);
            unsigned* p = &As_[r * OPAD + k4];
            p[0] = f2tf(av.x); p[1] = f2tf(av.y); p[2] = f2tf(av.z); p[3] = f2tf(av.w);
        }
#pragma unroll
        for (int it = 0; it < 2; it++) {
            int idx = it * 256 + tid;
            int k = idx >> 4, d4 = (idx & 15) * 4;
            float4 vv = *(const float4*)(vbase + (size_t)(k0 + k) * vstride + d4);
            unsigned* ph = &Vh[k * VPAD + d4];
            unsigned* pl = &Vl[k * VPAD + d4];
            split_tf(vv.x, ph[0], pl[0]);
            split_tf(vv.y, ph[1], pl[1]);
            split_tf(vv.z, ph[2], pl[2]);
            split_tf(vv.w, ph[3], pl[3]);
        }
        __syncthreads();
#pragma unroll
        for (int ks = 0; ks < 4; ks++) {
            const int kb = ks * 8;
            unsigned a[4][4], bh2[2][2], bl2[2][2];
#pragma unroll
            for (int i = 0; i < 4; i++) {
                int m = wr * 64 + i * 16 + (lane >> 2);
                int c = kb + (lane & 3);
                a[i][0] = As_[m * OPAD + c];
                a[i][1] = As_[(m + 8) * OPAD + c];
                a[i][2] = As_[m * OPAD + c + 4];
                a[i][3] = As_[(m + 8) * OPAD + c + 4];
            }
#pragma unroll
            for (int j = 0; j < 2; j++) {
                int n = wc * 16 + j * 8 + (lane >> 2);
                bh2[j][0] = Vh[(kb + (lane & 3)) * VPAD + n];
                bh2[j][1] = Vh[(kb + (lane & 3) + 4) * VPAD + n];
                bl2[j][0] = Vl[(kb + (lane & 3)) * VPAD + n];
                bl2[j][1] = Vl[(kb + (lane & 3) + 4) * VPAD + n];
            }
#pragma unroll
            for (int i = 0; i < 4; i++)
#pragma unroll
                for (int j = 0; j < 2; j++) {
                    mma_tf32(acc[i][j], a[i], bh2[j]);
                    mma_tf32(acc[i][j], a[i], bl2[j]);
                }
        }
        __syncthreads();
    }
#pragma unroll
    for (int i = 0; i < 4; i++) {
        int row = wr * 64 + i * 16 + (lane >> 2);
#pragma unroll
        for (int j = 0; j < 2; j++) {
            int col = wc * 16 + j * 8 + (lane & 3) * 2;
            float* p0 = obase + (size_t)row * ostride + col;
            float* p1 = obase + (size_t)(row + 8) * ostride + col;
            if (MODE == 0) {
                *(float2*)p0 = make_float2(acc[i][j][0], acc[i][j][1]);
                *(float2*)p1 = make_float2(acc[i][j][2], acc[i][j][3]);
            } else {
                float2 o0 = *(float2*)p0, o1 = *(float2*)p1;
                o0.x += acc[i][j][0]; o0.y += acc[i][j][1];
                o1.x += acc[i][j][2]; o1.y += acc[i][j][3];
                *(float2*)p0 = o0; *(float2*)p1 = o1;
            }
        }
    }
}

// ---------------- launch ----------------
extern "C" void kernel_launch(void* const* d_in, const int* in_sizes, int n_in,
                              void* d_out, int out_size) {
    const float* x = (const float*)d_in[0];
    const float* w = (const float*)d_in[1];
    float* out = (float*)d_out;

    float* scores;
    cudaGetSymbolAddress((void**)&scores, g_scores);

    k_zero<<<1, 1>>>();
    k_reduce<<<1024, 256>>>(x);
    k_finalize<<<1, 1>>>();
    k_prep_x<<<2048, 256>>>(x);
    k_prep_w<<<(NOUT * KDIM + 255) / 256, 256>>>(w);
    k_gemm2<<<dim3(NOUT / 128, MTOT / 128), 256>>>();
    k_scores1<<<4096, 256>>>(scores);
    k_scores2_sm<<<4096, 256>>>(scores);
    k_out_tf<0><<<4096, 256>>>(scores, out);
    k_out_tf<1><<<4096, 256>>>(scores, out);
}